// round 3
// baseline (speedup 1.0000x reference)
#include <cuda_runtime.h>

#define V_  50257
#define H_  768
#define B_  16
#define T_  128
#define G_  3072          // 4*H
#define KX  1536          // 2*H
#define MROWS 2048        // B*T

// ---------------- scratch (no cudaMalloc allowed) ----------------
__device__ float g_xg[(long)MROWS * G_];   // 25 MB: input-side gate projections
__device__ float g_gates[B_ * G_];         // per-step h @ W_hh^T
__device__ float g_c[B_ * H_];             // running cell state
__device__ float g_lse[MROWS];             // per-row logsumexp
__device__ int   g_last[B_];               // last attended index per example

// ---------------- fast exp (FMA-only, avoids MUFU bottleneck) ----------------
__device__ __forceinline__ float fexp(float x) {
    // valid for x <= 0 (we feed x - rowmax); clamp tail
    x = fmaxf(x, -20.0f);
    float t  = x * 1.4426950408889634f;        // x * log2(e)
    float z  = t + 12582912.0f;                // round-to-nearest via magic number
    float nf = z - 12582912.0f;
    float f  = t - nf;                         // f in [-0.5, 0.5]
    int   n  = (int)nf;
    // 2^f, degree-5 Taylor in ln2 (max err ~2e-6 on the interval)
    float p = fmaf(0.00133335581f, f, 0.00961812911f);
    p = fmaf(p, f, 0.0555041087f);
    p = fmaf(p, f, 0.240226507f);
    p = fmaf(p, f, 0.69314718056f);
    p = fmaf(p, f, 1.0f);
    return p * __int_as_float((n + 127) << 23);
}

// ---------------- setup: copy c0, compute last index ----------------
__global__ void setup_k(const float* __restrict__ dctx, const int* __restrict__ mask) {
    int idx = blockIdx.x * 256 + threadIdx.x;
    if (idx < B_ * H_) g_c[idx] = dctx[idx];
    if (idx >= B_ * H_ && idx < B_ * H_ + B_) {
        int b = idx - B_ * H_;
        int s = 0;
        for (int t = 0; t < T_; t++) s += mask[b * T_ + t];
        g_last[b] = s - 1;
    }
}

// ---------------- GEMM 1: xg = [emb(ids) || append] @ W_ih^T + b_ih ----------------
// 128x128 tile, BK=16, 8x8 per-thread register tile, fused embedding gather.
__global__ __launch_bounds__(256) void xg_gemm(
    const int*   __restrict__ ids,
    const float* __restrict__ emb,
    const float* __restrict__ app,
    const float* __restrict__ Wih,
    const float* __restrict__ bih)
{
    __shared__ __align__(16) float As[16 * 132];
    __shared__ __align__(16) float Bs[16 * 132];
    int tid = threadIdx.x;
    int n0 = blockIdx.x * 128;
    int m0 = blockIdx.y * 128;
    int tx = tid & 15, ty = tid >> 4;

    float acc[8][8];
#pragma unroll
    for (int i = 0; i < 8; i++)
#pragma unroll
        for (int j = 0; j < 8; j++) acc[i][j] = 0.0f;

    for (int k0 = 0; k0 < KX; k0 += 16) {
        // A tile (gathered): rows m0..m0+127, k0..k0+15
#pragma unroll
        for (int i = 0; i < 2; i++) {
            int f4 = tid + i * 256;
            int row = f4 >> 2, kq = f4 & 3;
            int k = k0 + kq * 4;
            int m = m0 + row;
            const float* p;
            if (k < H_) p = emb + (long)ids[m] * H_ + k;
            else        p = app + (long)(m >> 7) * H_ + (k - H_);
            float4 v = *(const float4*)p;
            As[(kq * 4 + 0) * 132 + row] = v.x;
            As[(kq * 4 + 1) * 132 + row] = v.y;
            As[(kq * 4 + 2) * 132 + row] = v.z;
            As[(kq * 4 + 3) * 132 + row] = v.w;
        }
        // B tile: W_ih rows n0..n0+127
#pragma unroll
        for (int i = 0; i < 2; i++) {
            int f4 = tid + i * 256;
            int row = f4 >> 2, kq = f4 & 3;
            int k = k0 + kq * 4;
            float4 v = *(const float4*)(Wih + (long)(n0 + row) * KX + k);
            Bs[(kq * 4 + 0) * 132 + row] = v.x;
            Bs[(kq * 4 + 1) * 132 + row] = v.y;
            Bs[(kq * 4 + 2) * 132 + row] = v.z;
            Bs[(kq * 4 + 3) * 132 + row] = v.w;
        }
        __syncthreads();
#pragma unroll
        for (int kk = 0; kk < 16; kk++) {
            float4 a0 = *(const float4*)&As[kk * 132 + ty * 8];
            float4 a1 = *(const float4*)&As[kk * 132 + ty * 8 + 4];
            float4 b0 = *(const float4*)&Bs[kk * 132 + tx * 8];
            float4 b1 = *(const float4*)&Bs[kk * 132 + tx * 8 + 4];
            float a[8] = {a0.x, a0.y, a0.z, a0.w, a1.x, a1.y, a1.z, a1.w};
            float b[8] = {b0.x, b0.y, b0.z, b0.w, b1.x, b1.y, b1.z, b1.w};
#pragma unroll
            for (int i = 0; i < 8; i++)
#pragma unroll
                for (int j = 0; j < 8; j++)
                    acc[i][j] = fmaf(a[i], b[j], acc[i][j]);
        }
        __syncthreads();
    }
#pragma unroll
    for (int i = 0; i < 8; i++) {
        int m = m0 + ty * 8 + i;
        float* cp = g_xg + (long)m * G_ + n0 + tx * 8;
#pragma unroll
        for (int j4 = 0; j4 < 8; j4 += 4) {
            float4 bv = *(const float4*)(bih + n0 + tx * 8 + j4);
            float4 st;
            st.x = acc[i][j4 + 0] + bv.x;
            st.y = acc[i][j4 + 1] + bv.y;
            st.z = acc[i][j4 + 2] + bv.z;
            st.w = acc[i][j4 + 3] + bv.w;
            *(float4*)(cp + j4) = st;
        }
    }
}

// ---------------- per-step: gates_mm = h @ W_hh^T  (M=16, N=3072, K=768) ----------------
// Each warp owns 2 output rows; lanes parallelize K (coalesced W loads, broadcast-free),
// then butterfly-reduce. W_hh read exactly once per step (L2 resident).
__global__ __launch_bounds__(256) void gates_mm(
    const float* __restrict__ hsrc, int hstride,
    const float* __restrict__ Whh)
{
    __shared__ __align__(16) float hs[B_ * H_];   // 48 KB
    int tid = threadIdx.x;
    for (int i = tid; i < B_ * H_; i += 256) {
        int b = i / H_, u = i - b * H_;
        hs[i] = hsrc[(long)b * hstride + u];
    }
    __syncthreads();

    int wid = tid >> 5, lane = tid & 31;
    int r0 = blockIdx.x * 16 + wid * 2;
    int r1 = r0 + 1;
    const float4* w0p = (const float4*)(Whh + (long)r0 * H_);
    const float4* w1p = (const float4*)(Whh + (long)r1 * H_);
    const float4* h4  = (const float4*)hs;

    float acc0[16], acc1[16];
#pragma unroll
    for (int b = 0; b < 16; b++) { acc0[b] = 0.0f; acc1[b] = 0.0f; }

#pragma unroll
    for (int ch = 0; ch < 6; ch++) {
        int k4 = ch * 32 + lane;
        float4 w0 = w0p[k4];
        float4 w1 = w1p[k4];
#pragma unroll
        for (int b = 0; b < 16; b++) {
            float4 h = h4[b * 192 + k4];
            acc0[b] = fmaf(w0.x, h.x, fmaf(w0.y, h.y, fmaf(w0.z, h.z, fmaf(w0.w, h.w, acc0[b]))));
            acc1[b] = fmaf(w1.x, h.x, fmaf(w1.y, h.y, fmaf(w1.z, h.z, fmaf(w1.w, h.w, acc1[b]))));
        }
    }
#pragma unroll
    for (int b = 0; b < 16; b++) {
        float v0 = acc0[b], v1 = acc1[b];
#pragma unroll
        for (int off = 16; off; off >>= 1) {
            v0 += __shfl_xor_sync(0xffffffffu, v0, off);
            v1 += __shfl_xor_sync(0xffffffffu, v1, off);
        }
        if (lane == b) {
            g_gates[b * G_ + r0] = v0;
            g_gates[b * G_ + r1] = v1;
        }
    }
}

// ---------------- per-step pointwise LSTM cell ----------------
__global__ void lstm_pw(int t, float* __restrict__ allh, float* __restrict__ selctx,
                        const float* __restrict__ bhh)
{
    int idx = blockIdx.x * 256 + threadIdx.x;
    if (idx >= B_ * H_) return;
    int b = idx / H_, u = idx - b * H_;
    long m = (long)b * T_ + t;
    const float* xr = g_xg + m * G_;
    const float* gr = g_gates + (long)b * G_;
    float xi = gr[u]          + xr[u]          + bhh[u];
    float xf = gr[H_ + u]     + xr[H_ + u]     + bhh[H_ + u];
    float xg = gr[2 * H_ + u] + xr[2 * H_ + u] + bhh[2 * H_ + u];
    float xo = gr[3 * H_ + u] + xr[3 * H_ + u] + bhh[3 * H_ + u];
    float si = 1.0f / (1.0f + expf(-xi));
    float sf = 1.0f / (1.0f + expf(-xf));
    float so = 1.0f / (1.0f + expf(-xo));
    float tg = tanhf(xg);
    float c = sf * g_c[idx] + si * tg;
    float h = so * tanhf(c);
    g_c[idx] = c;
    allh[m * H_ + u] = h;
    if (t == g_last[b]) selctx[idx] = c;
}

// ---------------- GEMM 3: logits = all_hiddens @ lm_w^T + lm_b (into lprobs region) ----------------
__global__ __launch_bounds__(256) void logits_gemm(
    const float* __restrict__ Ah,
    const float* __restrict__ lmw,
    const float* __restrict__ lmb,
    float* __restrict__ lp)
{
    __shared__ __align__(16) float As[16 * 132];
    __shared__ __align__(16) float Bs[16 * 132];
    int tid = threadIdx.x;
    int n0 = blockIdx.x * 128;
    int m0 = blockIdx.y * 128;
    int tx = tid & 15, ty = tid >> 4;

    float acc[8][8];
#pragma unroll
    for (int i = 0; i < 8; i++)
#pragma unroll
        for (int j = 0; j < 8; j++) acc[i][j] = 0.0f;

    for (int k0 = 0; k0 < H_; k0 += 16) {
#pragma unroll
        for (int i = 0; i < 2; i++) {
            int f4 = tid + i * 256;
            int row = f4 >> 2, kq = f4 & 3;
            int k = k0 + kq * 4;
            float4 v = *(const float4*)(Ah + (long)(m0 + row) * H_ + k);
            As[(kq * 4 + 0) * 132 + row] = v.x;
            As[(kq * 4 + 1) * 132 + row] = v.y;
            As[(kq * 4 + 2) * 132 + row] = v.z;
            As[(kq * 4 + 3) * 132 + row] = v.w;
        }
#pragma unroll
        for (int i = 0; i < 2; i++) {
            int f4 = tid + i * 256;
            int row = f4 >> 2, kq = f4 & 3;
            int k = k0 + kq * 4;
            int n = n0 + row;
            float4 v = make_float4(0.f, 0.f, 0.f, 0.f);
            if (n < V_) v = *(const float4*)(lmw + (long)n * H_ + k);
            Bs[(kq * 4 + 0) * 132 + row] = v.x;
            Bs[(kq * 4 + 1) * 132 + row] = v.y;
            Bs[(kq * 4 + 2) * 132 + row] = v.z;
            Bs[(kq * 4 + 3) * 132 + row] = v.w;
        }
        __syncthreads();
#pragma unroll
        for (int kk = 0; kk < 16; kk++) {
            float4 a0 = *(const float4*)&As[kk * 132 + ty * 8];
            float4 a1 = *(const float4*)&As[kk * 132 + ty * 8 + 4];
            float4 b0 = *(const float4*)&Bs[kk * 132 + tx * 8];
            float4 b1 = *(const float4*)&Bs[kk * 132 + tx * 8 + 4];
            float a[8] = {a0.x, a0.y, a0.z, a0.w, a1.x, a1.y, a1.z, a1.w};
            float b[8] = {b0.x, b0.y, b0.z, b0.w, b1.x, b1.y, b1.z, b1.w};
#pragma unroll
            for (int i = 0; i < 8; i++)
#pragma unroll
                for (int j = 0; j < 8; j++)
                    acc[i][j] = fmaf(a[i], b[j], acc[i][j]);
        }
        __syncthreads();
    }
    // scalar stores (row stride 50257 is odd -> no float4 alignment)
#pragma unroll
    for (int i = 0; i < 8; i++) {
        long m = m0 + ty * 8 + i;
        float* cp = lp + m * V_;
#pragma unroll
        for (int j = 0; j < 8; j++) {
            int n = n0 + tx * 8 + j;
            if (n < V_) cp[n] = acc[i][j] + lmb[n];
        }
    }
}

// ---------------- log-softmax: per-row max + sum(exp), then in-place subtract ----------------
__global__ void lse_k(const float* __restrict__ lp) {
    __shared__ float red[256];
    int m = blockIdx.x;
    int tid = threadIdx.x;
    const float* row = lp + (long)m * V_;
    float mx = -1e30f;
    for (int j = tid; j < V_; j += 256) mx = fmaxf(mx, row[j]);
    red[tid] = mx; __syncthreads();
    for (int s = 128; s; s >>= 1) { if (tid < s) red[tid] = fmaxf(red[tid], red[tid + s]); __syncthreads(); }
    mx = red[0];
    __syncthreads();
    float sum = 0.0f;
    for (int j = tid; j < V_; j += 256) sum += fexp(row[j] - mx);
    red[tid] = sum; __syncthreads();
    for (int s = 128; s; s >>= 1) { if (tid < s) red[tid] += red[tid + s]; __syncthreads(); }
    if (tid == 0) g_lse[m] = mx + logf(red[0]);
}

__global__ void sub_k(float* __restrict__ lp) {
    int m = blockIdx.y;
    int j = blockIdx.x * 256 + threadIdx.x;
    if (j < V_) lp[(long)m * V_ + j] -= g_lse[m];
}

// ---------------- launch ----------------
extern "C" void kernel_launch(void* const* d_in, const int* in_sizes, int n_in,
                              void* d_out, int out_size)
{
    const int*   ids  = (const int*)d_in[0];
    const int*   mask = (const int*)d_in[1];
    const float* dh   = (const float*)d_in[2];
    const float* dc   = (const float*)d_in[3];
    const float* dapp = (const float*)d_in[4];
    const float* emb  = (const float*)d_in[5];
    const float* Wih  = (const float*)d_in[6];
    const float* Whh  = (const float*)d_in[7];
    const float* bih  = (const float*)d_in[8];
    const float* bhh  = (const float*)d_in[9];
    const float* lmw  = (const float*)d_in[10];
    const float* lmb  = (const float*)d_in[11];
    (void)in_sizes; (void)n_in; (void)out_size;

    float* out    = (float*)d_out;
    float* allh   = out;                              // [B,T,H]
    float* selctx = out + (long)MROWS * H_;           // [B,H]
    float* lp     = selctx + B_ * H_;                 // [B,T,V]

    setup_k<<<49, 256>>>(dc, mask);
    xg_gemm<<<dim3(G_ / 128, MROWS / 128), 256>>>(ids, emb, dapp, Wih, bih);

    for (int t = 0; t < T_; t++) {
        const float* hsrc = (t == 0) ? dh : (allh + (long)(t - 1) * H_);
        int hstride = (t == 0) ? H_ : T_ * H_;
        gates_mm<<<192, 256>>>(hsrc, hstride, Whh);
        lstm_pw<<<48, 256>>>(t, allh, selctx, bhh);
    }

    logits_gemm<<<dim3((V_ + 127) / 128, MROWS / 128), 256>>>(allh, lmw, lmb, lp);
    lse_k<<<MROWS, 256>>>(lp);
    sub_k<<<dim3((V_ + 255) / 256, MROWS), 256>>>(lp);
}

// round 4
// speedup vs baseline: 1.0009x; 1.0009x over previous
#include <cuda_runtime.h>

#define V_  50257
#define H_  768
#define B_  16
#define T_  128
#define G_  3072          // 4*H
#define KX  1536          // 2*H
#define MROWS 2048        // B*T

// ---------------- scratch (no cudaMalloc allowed) ----------------
__device__ float g_xg[(long)MROWS * G_];   // 25 MB: input-side gate projections
__device__ float g_gates[B_ * G_];         // per-step h @ W_hh^T
__device__ float g_c[B_ * H_];             // running cell state
__device__ float g_lse[MROWS];             // per-row logsumexp
__device__ int   g_last[B_];               // last attended index per example

// ---------------- fast exp (FMA-only, avoids MUFU bottleneck) ----------------
__device__ __forceinline__ float fexp(float x) {
    // valid for x <= 0 (we feed x - rowmax); clamp tail
    x = fmaxf(x, -20.0f);
    float t  = x * 1.4426950408889634f;        // x * log2(e)
    float z  = t + 12582912.0f;                // round-to-nearest via magic number
    float nf = z - 12582912.0f;
    float f  = t - nf;                         // f in [-0.5, 0.5]
    int   n  = (int)nf;
    // 2^f, degree-5 Taylor in ln2 (max err ~2e-6 on the interval)
    float p = fmaf(0.00133335581f, f, 0.00961812911f);
    p = fmaf(p, f, 0.0555041087f);
    p = fmaf(p, f, 0.240226507f);
    p = fmaf(p, f, 0.69314718056f);
    p = fmaf(p, f, 1.0f);
    return p * __int_as_float((n + 127) << 23);
}

// ---------------- setup: copy c0, compute last index ----------------
__global__ void setup_k(const float* __restrict__ dctx, const int* __restrict__ mask) {
    int idx = blockIdx.x * 256 + threadIdx.x;
    if (idx < B_ * H_) g_c[idx] = dctx[idx];
    if (idx >= B_ * H_ && idx < B_ * H_ + B_) {
        int b = idx - B_ * H_;
        int s = 0;
        for (int t = 0; t < T_; t++) s += mask[b * T_ + t];
        g_last[b] = s - 1;
    }
}

// ---------------- GEMM 1: xg = [emb(ids) || append] @ W_ih^T + b_ih ----------------
// 128x128 tile, BK=16, 8x8 per-thread register tile, fused embedding gather.
__global__ __launch_bounds__(256) void xg_gemm(
    const int*   __restrict__ ids,
    const float* __restrict__ emb,
    const float* __restrict__ app,
    const float* __restrict__ Wih,
    const float* __restrict__ bih)
{
    __shared__ __align__(16) float As[16 * 132];
    __shared__ __align__(16) float Bs[16 * 132];
    int tid = threadIdx.x;
    int n0 = blockIdx.x * 128;
    int m0 = blockIdx.y * 128;
    int tx = tid & 15, ty = tid >> 4;

    float acc[8][8];
#pragma unroll
    for (int i = 0; i < 8; i++)
#pragma unroll
        for (int j = 0; j < 8; j++) acc[i][j] = 0.0f;

    for (int k0 = 0; k0 < KX; k0 += 16) {
        // A tile (gathered): rows m0..m0+127, k0..k0+15
#pragma unroll
        for (int i = 0; i < 2; i++) {
            int f4 = tid + i * 256;
            int row = f4 >> 2, kq = f4 & 3;
            int k = k0 + kq * 4;
            int m = m0 + row;
            const float* p;
            if (k < H_) p = emb + (long)ids[m] * H_ + k;
            else        p = app + (long)(m >> 7) * H_ + (k - H_);
            float4 v = *(const float4*)p;
            As[(kq * 4 + 0) * 132 + row] = v.x;
            As[(kq * 4 + 1) * 132 + row] = v.y;
            As[(kq * 4 + 2) * 132 + row] = v.z;
            As[(kq * 4 + 3) * 132 + row] = v.w;
        }
        // B tile: W_ih rows n0..n0+127
#pragma unroll
        for (int i = 0; i < 2; i++) {
            int f4 = tid + i * 256;
            int row = f4 >> 2, kq = f4 & 3;
            int k = k0 + kq * 4;
            float4 v = *(const float4*)(Wih + (long)(n0 + row) * KX + k);
            Bs[(kq * 4 + 0) * 132 + row] = v.x;
            Bs[(kq * 4 + 1) * 132 + row] = v.y;
            Bs[(kq * 4 + 2) * 132 + row] = v.z;
            Bs[(kq * 4 + 3) * 132 + row] = v.w;
        }
        __syncthreads();
#pragma unroll
        for (int kk = 0; kk < 16; kk++) {
            float4 a0 = *(const float4*)&As[kk * 132 + ty * 8];
            float4 a1 = *(const float4*)&As[kk * 132 + ty * 8 + 4];
            float4 b0 = *(const float4*)&Bs[kk * 132 + tx * 8];
            float4 b1 = *(const float4*)&Bs[kk * 132 + tx * 8 + 4];
            float a[8] = {a0.x, a0.y, a0.z, a0.w, a1.x, a1.y, a1.z, a1.w};
            float b[8] = {b0.x, b0.y, b0.z, b0.w, b1.x, b1.y, b1.z, b1.w};
#pragma unroll
            for (int i = 0; i < 8; i++)
#pragma unroll
                for (int j = 0; j < 8; j++)
                    acc[i][j] = fmaf(a[i], b[j], acc[i][j]);
        }
        __syncthreads();
    }
#pragma unroll
    for (int i = 0; i < 8; i++) {
        int m = m0 + ty * 8 + i;
        float* cp = g_xg + (long)m * G_ + n0 + tx * 8;
#pragma unroll
        for (int j4 = 0; j4 < 8; j4 += 4) {
            float4 bv = *(const float4*)(bih + n0 + tx * 8 + j4);
            float4 st;
            st.x = acc[i][j4 + 0] + bv.x;
            st.y = acc[i][j4 + 1] + bv.y;
            st.z = acc[i][j4 + 2] + bv.z;
            st.w = acc[i][j4 + 3] + bv.w;
            *(float4*)(cp + j4) = st;
        }
    }
}

// ---------------- per-step: gates_mm = h @ W_hh^T  (M=16, N=3072, K=768) ----------------
// Each warp owns 2 output rows; lanes parallelize K (coalesced W loads, broadcast-free),
// then butterfly-reduce. W_hh read exactly once per step (L2 resident).
__global__ __launch_bounds__(256) void gates_mm(
    const float* __restrict__ hsrc, int hstride,
    const float* __restrict__ Whh)
{
    __shared__ __align__(16) float hs[B_ * H_];   // 48 KB
    int tid = threadIdx.x;
    for (int i = tid; i < B_ * H_; i += 256) {
        int b = i / H_, u = i - b * H_;
        hs[i] = hsrc[(long)b * hstride + u];
    }
    __syncthreads();

    int wid = tid >> 5, lane = tid & 31;
    int r0 = blockIdx.x * 16 + wid * 2;
    int r1 = r0 + 1;
    const float4* w0p = (const float4*)(Whh + (long)r0 * H_);
    const float4* w1p = (const float4*)(Whh + (long)r1 * H_);
    const float4* h4  = (const float4*)hs;

    float acc0[16], acc1[16];
#pragma unroll
    for (int b = 0; b < 16; b++) { acc0[b] = 0.0f; acc1[b] = 0.0f; }

#pragma unroll
    for (int ch = 0; ch < 6; ch++) {
        int k4 = ch * 32 + lane;
        float4 w0 = w0p[k4];
        float4 w1 = w1p[k4];
#pragma unroll
        for (int b = 0; b < 16; b++) {
            float4 h = h4[b * 192 + k4];
            acc0[b] = fmaf(w0.x, h.x, fmaf(w0.y, h.y, fmaf(w0.z, h.z, fmaf(w0.w, h.w, acc0[b]))));
            acc1[b] = fmaf(w1.x, h.x, fmaf(w1.y, h.y, fmaf(w1.z, h.z, fmaf(w1.w, h.w, acc1[b]))));
        }
    }
#pragma unroll
    for (int b = 0; b < 16; b++) {
        float v0 = acc0[b], v1 = acc1[b];
#pragma unroll
        for (int off = 16; off; off >>= 1) {
            v0 += __shfl_xor_sync(0xffffffffu, v0, off);
            v1 += __shfl_xor_sync(0xffffffffu, v1, off);
        }
        if (lane == b) {
            g_gates[b * G_ + r0] = v0;
            g_gates[b * G_ + r1] = v1;
        }
    }
}

// ---------------- per-step pointwise LSTM cell ----------------
__global__ void lstm_pw(int t, float* __restrict__ allh, float* __restrict__ selctx,
                        const float* __restrict__ bhh)
{
    int idx = blockIdx.x * 256 + threadIdx.x;
    if (idx >= B_ * H_) return;
    int b = idx / H_, u = idx - b * H_;
    long m = (long)b * T_ + t;
    const float* xr = g_xg + m * G_;
    const float* gr = g_gates + (long)b * G_;
    float xi = gr[u]          + xr[u]          + bhh[u];
    float xf = gr[H_ + u]     + xr[H_ + u]     + bhh[H_ + u];
    float xg = gr[2 * H_ + u] + xr[2 * H_ + u] + bhh[2 * H_ + u];
    float xo = gr[3 * H_ + u] + xr[3 * H_ + u] + bhh[3 * H_ + u];
    float si = 1.0f / (1.0f + expf(-xi));
    float sf = 1.0f / (1.0f + expf(-xf));
    float so = 1.0f / (1.0f + expf(-xo));
    float tg = tanhf(xg);
    float c = sf * g_c[idx] + si * tg;
    float h = so * tanhf(c);
    g_c[idx] = c;
    allh[m * H_ + u] = h;
    if (t == g_last[b]) selctx[idx] = c;
}

// ---------------- GEMM 3: logits = all_hiddens @ lm_w^T + lm_b (into lprobs region) ----------------
__global__ __launch_bounds__(256) void logits_gemm(
    const float* __restrict__ Ah,
    const float* __restrict__ lmw,
    const float* __restrict__ lmb,
    float* __restrict__ lp)
{
    __shared__ __align__(16) float As[16 * 132];
    __shared__ __align__(16) float Bs[16 * 132];
    int tid = threadIdx.x;
    int n0 = blockIdx.x * 128;
    int m0 = blockIdx.y * 128;
    int tx = tid & 15, ty = tid >> 4;

    float acc[8][8];
#pragma unroll
    for (int i = 0; i < 8; i++)
#pragma unroll
        for (int j = 0; j < 8; j++) acc[i][j] = 0.0f;

    for (int k0 = 0; k0 < H_; k0 += 16) {
#pragma unroll
        for (int i = 0; i < 2; i++) {
            int f4 = tid + i * 256;
            int row = f4 >> 2, kq = f4 & 3;
            int k = k0 + kq * 4;
            float4 v = *(const float4*)(Ah + (long)(m0 + row) * H_ + k);
            As[(kq * 4 + 0) * 132 + row] = v.x;
            As[(kq * 4 + 1) * 132 + row] = v.y;
            As[(kq * 4 + 2) * 132 + row] = v.z;
            As[(kq * 4 + 3) * 132 + row] = v.w;
        }
#pragma unroll
        for (int i = 0; i < 2; i++) {
            int f4 = tid + i * 256;
            int row = f4 >> 2, kq = f4 & 3;
            int k = k0 + kq * 4;
            int n = n0 + row;
            float4 v = make_float4(0.f, 0.f, 0.f, 0.f);
            if (n < V_) v = *(const float4*)(lmw + (long)n * H_ + k);
            Bs[(kq * 4 + 0) * 132 + row] = v.x;
            Bs[(kq * 4 + 1) * 132 + row] = v.y;
            Bs[(kq * 4 + 2) * 132 + row] = v.z;
            Bs[(kq * 4 + 3) * 132 + row] = v.w;
        }
        __syncthreads();
#pragma unroll
        for (int kk = 0; kk < 16; kk++) {
            float4 a0 = *(const float4*)&As[kk * 132 + ty * 8];
            float4 a1 = *(const float4*)&As[kk * 132 + ty * 8 + 4];
            float4 b0 = *(const float4*)&Bs[kk * 132 + tx * 8];
            float4 b1 = *(const float4*)&Bs[kk * 132 + tx * 8 + 4];
            float a[8] = {a0.x, a0.y, a0.z, a0.w, a1.x, a1.y, a1.z, a1.w};
            float b[8] = {b0.x, b0.y, b0.z, b0.w, b1.x, b1.y, b1.z, b1.w};
#pragma unroll
            for (int i = 0; i < 8; i++)
#pragma unroll
                for (int j = 0; j < 8; j++)
                    acc[i][j] = fmaf(a[i], b[j], acc[i][j]);
        }
        __syncthreads();
    }
    // scalar stores (row stride 50257 is odd -> no float4 alignment)
#pragma unroll
    for (int i = 0; i < 8; i++) {
        long m = m0 + ty * 8 + i;
        float* cp = lp + m * V_;
#pragma unroll
        for (int j = 0; j < 8; j++) {
            int n = n0 + tx * 8 + j;
            if (n < V_) cp[n] = acc[i][j] + lmb[n];
        }
    }
}

// ---------------- log-softmax: per-row max + sum(exp), then in-place subtract ----------------
__global__ void lse_k(const float* __restrict__ lp) {
    __shared__ float red[256];
    int m = blockIdx.x;
    int tid = threadIdx.x;
    const float* row = lp + (long)m * V_;
    float mx = -1e30f;
    for (int j = tid; j < V_; j += 256) mx = fmaxf(mx, row[j]);
    red[tid] = mx; __syncthreads();
    for (int s = 128; s; s >>= 1) { if (tid < s) red[tid] = fmaxf(red[tid], red[tid + s]); __syncthreads(); }
    mx = red[0];
    __syncthreads();
    float sum = 0.0f;
    for (int j = tid; j < V_; j += 256) sum += fexp(row[j] - mx);
    red[tid] = sum; __syncthreads();
    for (int s = 128; s; s >>= 1) { if (tid < s) red[tid] += red[tid + s]; __syncthreads(); }
    if (tid == 0) g_lse[m] = mx + logf(red[0]);
}

__global__ void sub_k(float* __restrict__ lp) {
    int m = blockIdx.y;
    int j = blockIdx.x * 256 + threadIdx.x;
    if (j < V_) lp[(long)m * V_ + j] -= g_lse[m];
}

// ---------------- launch ----------------
extern "C" void kernel_launch(void* const* d_in, const int* in_sizes, int n_in,
                              void* d_out, int out_size)
{
    const int*   ids  = (const int*)d_in[0];
    const int*   mask = (const int*)d_in[1];
    const float* dh   = (const float*)d_in[2];
    const float* dc   = (const float*)d_in[3];
    const float* dapp = (const float*)d_in[4];
    const float* emb  = (const float*)d_in[5];
    const float* Wih  = (const float*)d_in[6];
    const float* Whh  = (const float*)d_in[7];
    const float* bih  = (const float*)d_in[8];
    const float* bhh  = (const float*)d_in[9];
    const float* lmw  = (const float*)d_in[10];
    const float* lmb  = (const float*)d_in[11];
    (void)in_sizes; (void)n_in; (void)out_size;

    float* out    = (float*)d_out;
    float* allh   = out;                              // [B,T,H]
    float* selctx = out + (long)MROWS * H_;           // [B,H]
    float* lp     = selctx + B_ * H_;                 // [B,T,V]

    setup_k<<<49, 256>>>(dc, mask);
    xg_gemm<<<dim3(G_ / 128, MROWS / 128), 256>>>(ids, emb, dapp, Wih, bih);

    for (int t = 0; t < T_; t++) {
        const float* hsrc = (t == 0) ? dh : (allh + (long)(t - 1) * H_);
        int hstride = (t == 0) ? H_ : T_ * H_;
        gates_mm<<<192, 256>>>(hsrc, hstride, Whh);
        lstm_pw<<<48, 256>>>(t, allh, selctx, bhh);
    }

    logits_gemm<<<dim3((V_ + 127) / 128, MROWS / 128), 256>>>(allh, lmw, lmb, lp);
    lse_k<<<MROWS, 256>>>(lp);
    sub_k<<<dim3((V_ + 255) / 256, MROWS), 256>>>(lp);
}